// round 5
// baseline (speedup 1.0000x reference)
#include <cuda_runtime.h>
#include <math.h>

#define B_DIM 8
#define L_DIM 2048
#define TOPK 30
#define NROWS (B_DIM * L_DIM)          // 16384
#define NEDGES (NROWS * TOPK)          // 491520
#define E_ELEMS ((size_t)NEDGES * 128) // 62914560
#define NFEAT 147                      // 144 rbf + 3 sh (pos folded into T)

// ---------------- device scratch (no allocations allowed) ----------------
__device__ int   g_Eidx[NEDGES];
__device__ float g_Dnb[NEDGES];
__device__ float g_SH[NROWS * 3];
__device__ float g_T[66 * 128];        // folded positional table: T[d][c]
__device__ float g_Wt[NFEAT * 128];    // W_edge transposed+reordered: Wt[f][c]
__device__ int   g_chainStride;        // 2 if chain_labels is int64, 1 if 32-bit

static __device__ __forceinline__ unsigned long long u64min(unsigned long long a, unsigned long long b) {
    return a < b ? a : b;
}

// XLA-bit-exact squared distance + sqrt: no FMA contraction, left-to-right adds.
static __device__ __forceinline__ float xla_dist(float dx, float dy, float dz) {
    float d2 = __fadd_rn(__fadd_rn(__fmul_rn(dx, dx), __fmul_rn(dy, dy)), __fmul_rn(dz, dz));
    return __fsqrt_rn(__fadd_rn(d2, 1e-6f));
}

// ---------------- prep: fold positional path + transpose weights + dtype probe ----------------
__global__ void prep_kernel(const float* __restrict__ W_edge,
                            const float* __restrict__ W_pos,
                            const float* __restrict__ b_pos,
                            const unsigned int* __restrict__ chains_w) {
    int tid = blockIdx.x * blockDim.x + threadIdx.x;
    if (tid == 0) {
        // int64 little-endian => every odd 32-bit word is a high word == 0.
        int stride = 2;
        for (int t = 1; t < 512; t += 2) {
            if (chains_w[t] != 0u) { stride = 1; break; }
        }
        g_chainStride = stride;
    }
    if (tid < 66 * 128) {
        int d = tid >> 7, c = tid & 127;
        float s = 0.f;
        #pragma unroll
        for (int p = 0; p < 16; p++)
            s += W_edge[c * 163 + p] * (W_pos[p * 66 + d] + b_pos[p]);
        g_T[tid] = s;   // g_T[d*128 + c]
    }
    int t2 = tid - 66 * 128;
    if (t2 >= 0 && t2 < NFEAT * 128) {
        int f = t2 >> 7, c = t2 & 127;
        int col = (f < 144) ? (16 + f) : (160 + (f - 144));
        g_Wt[t2] = W_edge[c * 163 + col];  // g_Wt[f*128 + c]
    }
}

// ---------------- spherical harmonics closed form ----------------
__global__ void sh_kernel(const float* __restrict__ Ca) {
    int idx = blockIdx.x * blockDim.x + threadIdx.x;
    if (idx >= NROWS) return;
    float x = Ca[idx * 3], y = Ca[idx * 3 + 1], z = Ca[idx * 3 + 2];
    float r = sqrtf(x * x + y * y + z * z);
    float phi = atan2f(y, x);
    float cp = cosf(phi);
    float s2 = 1.f - cp * cp;
    float cp2 = cp * cp;

    const float INV4PI = 0.07957747154594767f;
    float a00 = INV4PI;
    float f0 = sqrtf(a00 * a00);

    float a10 = 3.f * INV4PI, a11 = 0.5f * a10, a1m = 2.f * a10;
    float acc1 = a10 * a10 * cp2 + (a11 * a11 + 0.25f * a1m * a1m) * cp2 * s2;
    float f1 = sqrtf(acc1);

    float a20 = 5.f * INV4PI, a21 = a20 / 6.f, a2m1 = a20 * 6.f;
    float a22 = a20 / 24.f, a2m2 = a20 * 24.f;
    float p20 = 0.5f * (3.f * cp2 - 1.f);
    float c2 = cosf(2.f * phi);
    float acc2 = a20 * a20 * p20 * p20
               + (9.f * a21 * a21 + 0.25f * a2m1 * a2m1) * cp2 * cp2 * s2
               + (9.f * a22 * a22 + a2m2 * a2m2 * (1.f / 64.f)) * c2 * c2 * s2 * s2;
    float f2 = sqrtf(acc2);

    float q = z / r;
    bool bad = !(q >= -1.f && q <= 1.f);   // catches |q|>1 and NaN (r==0)
    if (bad || !(f0 == f0)) f0 = 0.f;
    if (bad || !(f1 == f1)) f1 = 0.f;
    if (bad || !(f2 == f2)) f2 = 0.f;
    g_SH[idx * 3]     = f0;
    g_SH[idx * 3 + 1] = f1;
    g_SH[idx * 3 + 2] = f2;
}

// ---------------- top-k: one block per (b,i) row ----------------
__global__ void __launch_bounds__(256) topk_kernel(const float* __restrict__ Ca,
                                                   const float* __restrict__ mask,
                                                   float* __restrict__ outIdx,
                                                   int writeIdx) {
    const int row = blockIdx.x;
    const int b = row >> 11, i = row & (L_DIM - 1);
    const int tid = threadIdx.x;
    const float* Cb = Ca + (size_t)(b << 11) * 3;
    float cx = Cb[i * 3], cy = Cb[i * 3 + 1], cz = Cb[i * 3 + 2];
    float mi = mask[row];

    float Dv[8], key[8], mm[8];
    float lmax = 0.f;
    #pragma unroll
    for (int t = 0; t < 8; t++) {
        int j = tid + (t << 8);
        // XLA order: dX = Ca[j] - Ca[i] (sign irrelevant after squaring);
        // exact mul/add chain, no contraction, matches jax bitwise.
        float dx = __fadd_rn(cx, -Cb[j * 3]);
        float dy = __fadd_rn(cy, -Cb[j * 3 + 1]);
        float dz = __fadd_rn(cz, -Cb[j * 3 + 2]);
        float sd = xla_dist(dx, dy, dz);
        float mij = __fmul_rn(mi, mask[(b << 11) + j]);
        float D = __fmul_rn(mij, sd);
        Dv[t] = D; mm[t] = mij;
        lmax = fmaxf(lmax, D);
    }

    __shared__ float sred[8];
    #pragma unroll
    for (int o = 16; o; o >>= 1) lmax = fmaxf(lmax, __shfl_xor_sync(0xffffffffu, lmax, o));
    if ((tid & 31) == 0) sred[tid >> 5] = lmax;
    __syncthreads();
    float Dmax = sred[0];
    #pragma unroll
    for (int w = 1; w < 8; w++) Dmax = fmaxf(Dmax, sred[w]);
    #pragma unroll
    for (int t = 0; t < 8; t++)
        key[t] = __fadd_rn(Dv[t], __fmul_rn(__fadd_rn(1.f, -mm[t]), Dmax));

    __shared__ unsigned long long swin[8];
    __syncthreads();

    for (int r = 0; r < TOPK; r++) {
        unsigned long long best = 0xFFFFFFFFFFFFFFFFull;
        #pragma unroll
        for (int t = 0; t < 8; t++) {
            unsigned long long cand =
                ((unsigned long long)__float_as_uint(key[t]) << 32) | (unsigned)(tid + (t << 8));
            best = u64min(best, cand);
        }
        #pragma unroll
        for (int o = 16; o; o >>= 1)
            best = u64min(best, __shfl_xor_sync(0xffffffffu, best, o));
        if ((tid & 31) == 0) swin[tid >> 5] = best;
        __syncthreads();
        unsigned long long wbest = swin[0];
        #pragma unroll
        for (int w = 1; w < 8; w++) wbest = u64min(wbest, swin[w]);
        int jw = (int)(wbest & 0xFFFFFFFFu);
        if ((jw & 255) == tid) {
            int t = jw >> 8;
            g_Eidx[row * TOPK + r] = jw;
            g_Dnb[row * TOPK + r] = key[t];   // == D_adjust value (ref semantics)
            if (writeIdx) outIdx[row * TOPK + r] = (float)jw;
            key[t] = __int_as_float(0x7F800000);  // +inf
        }
        __syncthreads();
    }
}

// ---------------- edge kernel: features + 147x128 GEMV + LayerNorm ----------------
#define EW 16               // warps per CTA (one row per warp)
#define FEAT_STRIDE 1184    // 148 * 8 floats per warp
#define SMEM_FLOATS (NFEAT * 128 + EW * FEAT_STRIDE)

__global__ void __launch_bounds__(512, 1)
edge_kernel(const float* __restrict__ Ca,
            const unsigned int* __restrict__ chains_w,
            const float* __restrict__ gamma,
            const float* __restrict__ beta,
            float* __restrict__ outE) {
    extern __shared__ float smem[];
    float* Wt = smem;
    const int warp = threadIdx.x >> 5, lane = threadIdx.x & 31;

    for (int idx = threadIdx.x; idx < NFEAT * 128; idx += 512) Wt[idx] = g_Wt[idx];
    __syncthreads();

    float* feats = smem + NFEAT * 128 + warp * FEAT_STRIDE;

    const int row = blockIdx.x * EW + warp;
    const int b = row >> 11, i = row & (L_DIM - 1);
    const float* Cb = Ca + (size_t)(b << 11) * 3;
    const int cstr = g_chainStride;

    float3 Ci  = make_float3(Cb[i * 3], Cb[i * 3 + 1], Cb[i * 3 + 2]);
    float3 Ci0 = (i > 0) ? make_float3(Cb[(i - 1) * 3], Cb[(i - 1) * 3 + 1], Cb[(i - 1) * 3 + 2])
                         : make_float3(0.f, 0.f, 0.f);
    float3 Ci2 = (i < L_DIM - 1) ? make_float3(Cb[(i + 1) * 3], Cb[(i + 1) * 3 + 1], Cb[(i + 1) * 3 + 2])
                                 : make_float3(0.f, 0.f, 0.f);
    unsigned int chi = chains_w[(size_t)row * cstr];

    // block (1..8) A/B source codes: 0=Ca_prev 1=Ca 2=Ca_next
    int li = (lane >= 1) ? ((lane - 1) & 7) : 0;
    int ac = (int)((0x22110020u >> (li << 2)) & 3u);
    int bc = (int)((0x10202120u >> (li << 2)) & 3u);
    float3 Apt = (ac == 0) ? Ci0 : ((ac == 1) ? Ci : Ci2);

    float4 g4  = *(const float4*)&gamma[lane << 2];
    float4 be4 = *(const float4*)&beta[lane << 2];

    for (int tile = 0; tile < 4; tile++) {
        const int ec = (tile < 3) ? 8 : 6;
        const int k0 = tile << 3;

        int jj = 0; float D0 = 0.f; int didx = 65;
        if (lane < ec) {
            jj = g_Eidx[row * TOPK + k0 + lane];
            D0 = g_Dnb[row * TOPK + k0 + lane];
            unsigned int cj = chains_w[(size_t)((b << 11) + jj) * cstr];
            int off = i - jj + 32;                  // residue_idx is arange(L)
            off = off < 0 ? 0 : (off > 64 ? 64 : off);
            didx = (chi == cj) ? off : 65;
        }

        // ---- feature generation: 9 distances -> 144 rbf + 3 sh per edge ----
        for (int e = 0; e < ec; e++) {
            int   je  = __shfl_sync(0xffffffffu, jj, e);
            float D0e = __shfl_sync(0xffffffffu, D0, e);
            float dv = D0e;                       // lane 0 = block 0 (D_neighbors)
            int jb = je + bc - 1;
            bool valid = (bc == 1) || (jb >= 0 && jb <= L_DIM - 1);
            float bx = 0.f, by = 0.f, bz = 0.f;
            if (lane >= 1 && lane <= 8 && valid) {
                bx = Cb[jb * 3]; by = Cb[jb * 3 + 1]; bz = Cb[jb * 3 + 2];
            }
            if (lane >= 1 && lane <= 8) {
                float dx = Apt.x - bx, dy = Apt.y - by, dz = Apt.z - bz;
                dv = sqrtf(dx * dx + dy * dy + dz * dz + 1e-6f);
            }
            #pragma unroll
            for (int t = 0; t < 5; t++) {
                int f = lane + (t << 5);
                int blk = f >> 4;
                float dd = __shfl_sync(0xffffffffu, dv, blk < 9 ? blk : 0);
                if (f < 144) {
                    float m = (float)(f & 15);
                    float u = (dd - (2.f + m * (4.f / 3.f))) * 0.8f;
                    feats[(f << 3) + e] = __expf(-u * u);
                }
            }
            if (lane < 3)
                feats[((144 + lane) << 3) + e] = g_SH[((b << 11) + je) * 3 + lane];
        }
        __syncwarp();

        // ---- GEMV: 147 feats x 128 channels, 8 edges per warp ----
        float4 Acc[8];
        #pragma unroll
        for (int e = 0; e < 8; e++) Acc[e] = make_float4(0.f, 0.f, 0.f, 0.f);

        #pragma unroll 3
        for (int f = 0; f < NFEAT; f++) {
            float4 w  = *(const float4*)&Wt[(f << 7) + (lane << 2)];
            float4 fa = *(const float4*)&feats[f << 3];
            float4 fb = *(const float4*)&feats[(f << 3) + 4];
            float fv[8] = {fa.x, fa.y, fa.z, fa.w, fb.x, fb.y, fb.z, fb.w};
            #pragma unroll
            for (int e = 0; e < 8; e++) {
                Acc[e].x = fmaf(fv[e], w.x, Acc[e].x);
                Acc[e].y = fmaf(fv[e], w.y, Acc[e].y);
                Acc[e].z = fmaf(fv[e], w.z, Acc[e].z);
                Acc[e].w = fmaf(fv[e], w.w, Acc[e].w);
            }
        }

        // ---- epilogue: + positional table, LayerNorm, store ----
        #pragma unroll
        for (int e = 0; e < 8; e++) {
            if (e >= ec) break;
            int de = __shfl_sync(0xffffffffu, didx, e);
            float4 t4 = *(const float4*)&g_T[(de << 7) + (lane << 2)];
            float x0 = Acc[e].x + t4.x, x1 = Acc[e].y + t4.y;
            float x2 = Acc[e].z + t4.z, x3 = Acc[e].w + t4.w;
            float s = x0 + x1 + x2 + x3;
            #pragma unroll
            for (int o = 16; o; o >>= 1) s += __shfl_xor_sync(0xffffffffu, s, o);
            float mu = s * (1.f / 128.f);
            float d0 = x0 - mu, d1 = x1 - mu, d2 = x2 - mu, d3 = x3 - mu;
            float ss = d0 * d0 + d1 * d1 + d2 * d2 + d3 * d3;
            #pragma unroll
            for (int o = 16; o; o >>= 1) ss += __shfl_xor_sync(0xffffffffu, ss, o);
            float rstd = rsqrtf(ss * (1.f / 128.f) + 1e-5f);
            float4 o4;
            o4.x = d0 * rstd * g4.x + be4.x;
            o4.y = d1 * rstd * g4.y + be4.y;
            o4.z = d2 * rstd * g4.z + be4.z;
            o4.w = d3 * rstd * g4.w + be4.w;
            *(float4*)&outE[(((size_t)row * TOPK) + k0 + e) * 128 + (lane << 2)] = o4;
        }
        __syncwarp();
    }
}

// ---------------- launch ----------------
extern "C" void kernel_launch(void* const* d_in, const int* in_sizes, int n_in,
                              void* d_out, int out_size) {
    const float* Ca     = (const float*)d_in[0];
    const float* mask   = (const float*)d_in[1];
    const unsigned int* chains_w = (const unsigned int*)d_in[3];
    const float* W_pos  = (const float*)d_in[4];
    const float* b_pos  = (const float*)d_in[5];
    const float* W_edge = (const float*)d_in[6];
    const float* gamma  = (const float*)d_in[7];
    const float* beta   = (const float*)d_in[8];
    float* out = (float*)d_out;

    int writeIdx = ((size_t)out_size >= E_ELEMS + (size_t)NEDGES) ? 1 : 0;

    prep_kernel<<<(66 * 128 + NFEAT * 128 + 255) / 256, 256>>>(W_edge, W_pos, b_pos, chains_w);
    sh_kernel<<<(NROWS + 255) / 256, 256>>>(Ca);
    topk_kernel<<<NROWS, 256>>>(Ca, mask, out + E_ELEMS, writeIdx);

    cudaFuncSetAttribute(edge_kernel, cudaFuncAttributeMaxDynamicSharedMemorySize,
                         SMEM_FLOATS * sizeof(float));
    edge_kernel<<<NROWS / EW, 512, SMEM_FLOATS * sizeof(float)>>>(
        Ca, chains_w, gamma, beta, out);
}